// round 6
// baseline (speedup 1.0000x reference)
#include <cuda_runtime.h>
#include <cuda_bf16.h>
#include <math.h>
#include <stdint.h>

// Problem constants
#define B_  2
#define S_  2048
#define H_  4096
#define NH_ 32
#define NKV_ 8
#define HD_ 128
#define M_  (B_ * S_)          // 4096 rows
#define QN_ (NH_ * HD_)        // 4096
#define KN_ (NKV_ * HD_)       // 1024

// Scratch (device globals; no allocations allowed)
__device__ float g_Q[M_ * QN_];
__device__ float g_K[M_ * KN_];
__device__ float g_V[M_ * KN_];
__device__ float g_AO[M_ * QN_];
__device__ float g_Xr[M_ * H_];
__device__ float g_Wq[H_ * QN_];
__device__ float g_Wk[H_ * KN_];
__device__ float g_Wv[H_ * KN_];
__device__ float g_Wo[QN_ * H_];
__device__ __nv_bfloat16 g_Khi[M_ * KN_], g_Klo[M_ * KN_];
__device__ __nv_bfloat16 g_Vhi[M_ * KN_], g_Vlo[M_ * KN_];

__device__ __forceinline__ float round_tf32_f(float f) {
    unsigned r;
    asm("cvt.rna.tf32.f32 %0, %1;" : "=r"(r) : "f"(f));
    return __uint_as_float(r);
}

__device__ __forceinline__ void split2(float x, float y, unsigned& hi, unsigned& lo)
{
    __nv_bfloat162 h = __floats2bfloat162_rn(x, y);
    float hx = __bfloat162float(h.x), hy = __bfloat162float(h.y);
    __nv_bfloat162 l = __floats2bfloat162_rn(x - hx, y - hy);
    hi = *(unsigned*)&h;
    lo = *(unsigned*)&l;
}

// grid-stride pre-round to tf32 grid
__global__ __launch_bounds__(256)
void preround_kernel(const float* __restrict__ in, float* __restrict__ out, int n)
{
    int i = (blockIdx.x * 256 + threadIdx.x) * 4;
    const int stride = gridDim.x * 1024;
    for (; i < n; i += stride) {
        float4 v = *(const float4*)(in + i);
        v.x = round_tf32_f(v.x);
        v.y = round_tf32_f(v.y);
        v.z = round_tf32_f(v.z);
        v.w = round_tf32_f(v.w);
        *(float4*)(out + i) = v;
    }
}

// f32 -> bf16 hi/lo split (row-major copy)
__global__ __launch_bounds__(256)
void split_kernel(const float* __restrict__ in, __nv_bfloat16* __restrict__ hi,
                  __nv_bfloat16* __restrict__ lo, int n)
{
    int i = (blockIdx.x * 256 + threadIdx.x) * 4;
    const int stride = gridDim.x * 1024;
    for (; i < n; i += stride) {
        float4 v = *(const float4*)(in + i);
        unsigned h01, l01, h23, l23;
        split2(v.x, v.y, h01, l01);
        split2(v.z, v.w, h23, l23);
        *(unsigned*)(hi + i)     = h01;
        *(unsigned*)(hi + i + 2) = h23;
        *(unsigned*)(lo + i)     = l01;
        *(unsigned*)(lo + i + 2) = l23;
    }
}

// ---------------------------------------------------------------------------
// TF32 tensor-core GEMM (R4, unchanged): inputs pre-rounded -> raw-bit MMA.
// ---------------------------------------------------------------------------
#define AS_STRIDE 20
#define BS_STRIDE 136
#define STAGE_FLOATS (128 * AS_STRIDE + 16 * BS_STRIDE)

__device__ __forceinline__ void mma_tf32(float& d0, float& d1, float& d2, float& d3,
                                         unsigned a0, unsigned a1, unsigned a2, unsigned a3,
                                         unsigned b0, unsigned b1)
{
    asm volatile(
        "mma.sync.aligned.m16n8k8.row.col.f32.tf32.tf32.f32 "
        "{%0,%1,%2,%3}, {%4,%5,%6,%7}, {%8,%9}, {%0,%1,%2,%3};"
        : "+f"(d0), "+f"(d1), "+f"(d2), "+f"(d3)
        : "r"(a0), "r"(a1), "r"(a2), "r"(a3), "r"(b0), "r"(b1));
}

__device__ __forceinline__ void cp_async16(void* smem_dst, const void* gsrc) {
    unsigned dst = (unsigned)__cvta_generic_to_shared(smem_dst);
    asm volatile("cp.async.cg.shared.global [%0], [%1], 16;" :: "r"(dst), "l"(gsrc));
}

__global__ __launch_bounds__(256)
void gemm_tf32(const float* __restrict__ A, const float* __restrict__ B,
               const float* __restrict__ bias, float* __restrict__ C,
               int M, int N, int K)
{
    __shared__ float smem[2 * STAGE_FLOATS];

    const int tid  = threadIdx.x;
    const int wid  = tid >> 5;
    const int lane = tid & 31;
    const int warp_m = (wid & 1) * 64;
    const int warp_n = (wid >> 1) * 32;
    const int brow = blockIdx.y * 128;
    const int bcol = blockIdx.x * 128;
    const int lr = lane >> 2;
    const int lc = lane & 3;

    float acc[4][4][4];
#pragma unroll
    for (int mt = 0; mt < 4; mt++)
#pragma unroll
        for (int nt = 0; nt < 4; nt++)
#pragma unroll
            for (int i = 0; i < 4; i++) acc[mt][nt][i] = 0.f;

    const int a_row0 = tid >> 2;
    const int a_col  = (tid & 3) * 4;
    const int b_row0 = tid >> 5;
    const int b_col  = (tid & 31) * 4;

    auto load_stage = [&](int s, int k0) {
        float* Asm = smem + s * STAGE_FLOATS;
        float* Bsm = Asm + 128 * AS_STRIDE;
#pragma unroll
        for (int it = 0; it < 2; it++) {
            int r = a_row0 + it * 64;
            cp_async16(&Asm[r * AS_STRIDE + a_col],
                       &A[(size_t)(brow + r) * K + k0 + a_col]);
        }
#pragma unroll
        for (int it = 0; it < 2; it++) {
            int r = b_row0 + it * 8;
            cp_async16(&Bsm[r * BS_STRIDE + b_col],
                       &B[(size_t)(k0 + r) * N + bcol + b_col]);
        }
        asm volatile("cp.async.commit_group;");
    };

    const int KT = K / 16;
    load_stage(0, 0);

    for (int kt = 0; kt < KT; kt++) {
        const int s = kt & 1;
        if (kt + 1 < KT) {
            load_stage(s ^ 1, (kt + 1) * 16);
            asm volatile("cp.async.wait_group 1;");
        } else {
            asm volatile("cp.async.wait_group 0;");
        }
        __syncthreads();

        const float* Asm = smem + s * STAGE_FLOATS;
        const float* Bsm = Asm + 128 * AS_STRIDE;

#pragma unroll
        for (int ks = 0; ks < 2; ks++) {
            const int k0 = ks * 8;
            unsigned af[4][4], bf[4][2];
#pragma unroll
            for (int mt = 0; mt < 4; mt++) {
                const float* ap = Asm + (warp_m + mt * 16 + lr) * AS_STRIDE + k0 + lc;
                af[mt][0] = __float_as_uint(ap[0]);
                af[mt][1] = __float_as_uint(ap[8 * AS_STRIDE]);
                af[mt][2] = __float_as_uint(ap[4]);
                af[mt][3] = __float_as_uint(ap[8 * AS_STRIDE + 4]);
            }
#pragma unroll
            for (int nt = 0; nt < 4; nt++) {
                const float* bp = Bsm + (k0 + lc) * BS_STRIDE + warp_n + nt * 8 + lr;
                bf[nt][0] = __float_as_uint(bp[0]);
                bf[nt][1] = __float_as_uint(bp[4 * BS_STRIDE]);
            }
#pragma unroll
            for (int mt = 0; mt < 4; mt++)
#pragma unroll
                for (int nt = 0; nt < 4; nt++)
                    mma_tf32(acc[mt][nt][0], acc[mt][nt][1], acc[mt][nt][2], acc[mt][nt][3],
                             af[mt][0], af[mt][1], af[mt][2], af[mt][3],
                             bf[nt][0], bf[nt][1]);
        }
        __syncthreads();
    }

#pragma unroll
    for (int mt = 0; mt < 4; mt++) {
#pragma unroll
        for (int nt = 0; nt < 4; nt++) {
            const int row0 = brow + warp_m + mt * 16 + lr;
            const int col  = bcol + warp_n + nt * 8 + lc * 2;
            const float b0 = bias ? bias[col]     : 0.f;
            const float b1 = bias ? bias[col + 1] : 0.f;
            float2 v0 = make_float2(acc[mt][nt][0] + b0, acc[mt][nt][1] + b1);
            float2 v1 = make_float2(acc[mt][nt][2] + b0, acc[mt][nt][3] + b1);
            *(float2*)&C[(size_t)row0 * N + col]       = v0;
            *(float2*)&C[(size_t)(row0 + 8) * N + col] = v1;
        }
    }
}

// ---------------------------------------------------------------------------
// RoPE: Q in-place (pre-scaled by 1/sqrt(HD)); K -> bf16 hi/lo globals.
// ---------------------------------------------------------------------------
__global__ __launch_bounds__(128)
void rope_kernel(float* __restrict__ Q, const float* __restrict__ Kf,
                 __nv_bfloat16* __restrict__ Khi, __nv_bfloat16* __restrict__ Klo,
                 const int* __restrict__ pos_ids)
{
    const int row  = blockIdx.x;
    const int head = blockIdx.y;
    const int d    = threadIdx.x;

    const int pos = pos_ids[row];
    const int i = d & 63;
    const float inv_freq = exp2f(-(float)(2 * i) * (1.0f / 128.0f) * 13.28771238f);
    const float ang = (float)pos * inv_freq;
    float c, s;
    sincosf(ang, &s, &c);

    if (head < NH_) {
        float* base = Q + (size_t)row * QN_ + head * HD_;
        const float x = base[d];
        const float other = (d < 64) ? -base[d + 64] : base[d - 64];
        const float v = (x * c + other * s) * 0.08838834764831845f;
        __syncthreads();
        base[d] = v;
    } else {
        const size_t off = (size_t)row * KN_ + (head - NH_) * HD_;
        const float x = Kf[off + d];
        const float other = (d < 64) ? -Kf[off + d + 64] : Kf[off + d - 64];
        const float v = x * c + other * s;
        const __nv_bfloat16 h = __float2bfloat16(v);
        Khi[off + d] = h;
        Klo[off + d] = __float2bfloat16(v - __bfloat162float(h));
    }
}

// ---------------------------------------------------------------------------
// Tensor-core flash attention, bf16x3; K/V pre-split in global, cp.async
// double-buffered tiles; 256 threads = 8 warps = 128 queries per block.
// ---------------------------------------------------------------------------
#define AT_THREADS 256
#define ATQ 128
#define ATK 64
#define KSTR 136
#define ABUF   (ATK * KSTR * 2)      // 17408 B per buffer
#define ASTAGE (4 * ABUF)            // Khi, Klo, Vhi, Vlo = 69632 B
#define ATT_SMEM (2 * ASTAGE)        // 139264 B

__device__ __forceinline__ void mma_bf16(float c[4], const unsigned a[4],
                                         unsigned b0, unsigned b1)
{
    asm volatile(
        "mma.sync.aligned.m16n8k16.row.col.f32.bf16.bf16.f32 "
        "{%0,%1,%2,%3}, {%4,%5,%6,%7}, {%8,%9}, {%0,%1,%2,%3};"
        : "+f"(c[0]), "+f"(c[1]), "+f"(c[2]), "+f"(c[3])
        : "r"(a[0]), "r"(a[1]), "r"(a[2]), "r"(a[3]), "r"(b0), "r"(b1));
}

__device__ __forceinline__ void ldsm4t(unsigned r[4], const void* p)
{
    unsigned a = (unsigned)__cvta_generic_to_shared(p);
    asm volatile(
        "ldmatrix.sync.aligned.m8n8.x4.trans.shared.b16 {%0,%1,%2,%3}, [%4];"
        : "=r"(r[0]), "=r"(r[1]), "=r"(r[2]), "=r"(r[3]) : "r"(a));
}

__global__ __launch_bounds__(AT_THREADS)
void attn_mma(const float* __restrict__ Q,
              const __nv_bfloat16* __restrict__ Khi, const __nv_bfloat16* __restrict__ Klo,
              const __nv_bfloat16* __restrict__ Vhi, const __nv_bfloat16* __restrict__ Vlo,
              float* __restrict__ AO)
{
    extern __shared__ char smraw[];

    const int qt = blockIdx.x, h = blockIdx.y, b = blockIdx.z;
    const int q0 = qt * ATQ;
    const int kvh = h >> 2;
    const int tid = threadIdx.x;
    const int w = tid >> 5, lane = tid & 31;
    const int lr = lane >> 2, lc = lane & 3;

    const int qrow0 = q0 + w * 16 + lr;
    const int qrow1 = qrow0 + 8;

    // ---- Q fragments (already scaled by rope), hi/lo split, in registers ----
    unsigned qa_hi[8][4], qa_lo[8][4];
    {
        const float* Q0 = Q + ((size_t)(b * S_) + qrow0) * QN_ + h * HD_;
        const float* Q1 = Q + ((size_t)(b * S_) + qrow1) * QN_ + h * HD_;
#pragma unroll
        for (int kt = 0; kt < 8; kt++) {
            float2 v;
            v = *(const float2*)(Q0 + kt * 16 + 2 * lc);
            split2(v.x, v.y, qa_hi[kt][0], qa_lo[kt][0]);
            v = *(const float2*)(Q1 + kt * 16 + 2 * lc);
            split2(v.x, v.y, qa_hi[kt][1], qa_lo[kt][1]);
            v = *(const float2*)(Q0 + kt * 16 + 2 * lc + 8);
            split2(v.x, v.y, qa_hi[kt][2], qa_lo[kt][2]);
            v = *(const float2*)(Q1 + kt * 16 + 2 * lc + 8);
            split2(v.x, v.y, qa_hi[kt][3], qa_lo[kt][3]);
        }
    }

    float m0 = -1e30f, m1 = -1e30f, l0 = 0.f, l1 = 0.f;
    float o[16][4];
#pragma unroll
    for (int i = 0; i < 16; i++)
#pragma unroll
        for (int j = 0; j < 4; j++) o[i][j] = 0.f;

    const int nTiles = q0 / ATK + 2;
    const int wEnd = q0 + w * 16 + 16;
    const int ldr = (lane & 7) + ((lane >> 3) & 1) * 8;
    const int ldc = ((lane >> 4) & 1) * 8;

    const size_t kv_base = (size_t)(b * S_) * KN_ + kvh * HD_;
    const uint32_t sb = (uint32_t)__cvta_generic_to_shared(smraw);

    // per-thread load decomposition: 4 chunks of 16B per buffer
    const int ch_row[4] = { (tid * 4 + 0) >> 4, (tid * 4 + 1) >> 4,
                            (tid * 4 + 2) >> 4, (tid * 4 + 3) >> 4 };
    const int ch_c16[4] = { (tid * 4 + 0) & 15, (tid * 4 + 1) & 15,
                            (tid * 4 + 2) & 15, (tid * 4 + 3) & 15 };

    auto load_tile = [&](int s, int kbase) {
        const size_t off = kv_base + (size_t)kbase * KN_;
        const uint32_t st = sb + s * ASTAGE;
#pragma unroll
        for (int j = 0; j < 4; j++) {
            const size_t g = off + (size_t)ch_row[j] * KN_ + ch_c16[j] * 8;
            const uint32_t d = st + ch_row[j] * (KSTR * 2) + ch_c16[j] * 16;
            asm volatile("cp.async.cg.shared.global [%0], [%1], 16;" :: "r"(d),            "l"(Khi + g));
            asm volatile("cp.async.cg.shared.global [%0], [%1], 16;" :: "r"(d + ABUF),     "l"(Klo + g));
            asm volatile("cp.async.cg.shared.global [%0], [%1], 16;" :: "r"(d + 2 * ABUF), "l"(Vhi + g));
            asm volatile("cp.async.cg.shared.global [%0], [%1], 16;" :: "r"(d + 3 * ABUF), "l"(Vlo + g));
        }
        asm volatile("cp.async.commit_group;");
    };

    load_tile(0, 0);

    for (int kt = 0; kt < nTiles; kt++) {
        const int kbase = kt * ATK;
        const int s = kt & 1;
        const bool active = kbase < wEnd;

        asm volatile("cp.async.wait_group 0;");
        __syncthreads();
        if (kt + 1 < nTiles) load_tile(s ^ 1, kbase + ATK);

        const __nv_bfloat16* sKhi = (const __nv_bfloat16*)(smraw + s * ASTAGE);
        const __nv_bfloat16* sKlo = (const __nv_bfloat16*)(smraw + s * ASTAGE + ABUF);
        const __nv_bfloat16* sVhi = (const __nv_bfloat16*)(smraw + s * ASTAGE + 2 * ABUF);
        const __nv_bfloat16* sVlo = (const __nv_bfloat16*)(smraw + s * ASTAGE + 3 * ABUF);

        if (active) {
            float sA[8][4];
#pragma unroll
            for (int nt = 0; nt < 8; nt++)
#pragma unroll
                for (int j = 0; j < 4; j++) sA[nt][j] = 0.f;

#pragma unroll
            for (int dkt = 0; dkt < 8; dkt++) {
#pragma unroll
                for (int nt = 0; nt < 8; nt++) {
                    const __nv_bfloat16* kh = sKhi + (nt * 8 + lr) * KSTR + dkt * 16 + 2 * lc;
                    const __nv_bfloat16* kl = sKlo + (nt * 8 + lr) * KSTR + dkt * 16 + 2 * lc;
                    unsigned bh0 = *(const unsigned*)kh;
                    unsigned bh1 = *(const unsigned*)(kh + 8);
                    unsigned bl0 = *(const unsigned*)kl;
                    unsigned bl1 = *(const unsigned*)(kl + 8);
                    mma_bf16(sA[nt], qa_hi[dkt], bh0, bh1);
                    mma_bf16(sA[nt], qa_hi[dkt], bl0, bl1);
                    mma_bf16(sA[nt], qa_lo[dkt], bh0, bh1);
                }
            }

            if (kbase + ATK > qrow0) {
#pragma unroll
                for (int nt = 0; nt < 8; nt++) {
                    const int j0 = kbase + nt * 8 + 2 * lc;
                    if (j0 > qrow0)     sA[nt][0] = -1e30f;
                    if (j0 + 1 > qrow0) sA[nt][1] = -1e30f;
                    if (j0 > qrow1)     sA[nt][2] = -1e30f;
                    if (j0 + 1 > qrow1) sA[nt][3] = -1e30f;
                }
            }

            float mt0 = -1e30f, mt1 = -1e30f;
#pragma unroll
            for (int nt = 0; nt < 8; nt++) {
                mt0 = fmaxf(mt0, fmaxf(sA[nt][0], sA[nt][1]));
                mt1 = fmaxf(mt1, fmaxf(sA[nt][2], sA[nt][3]));
            }
            mt0 = fmaxf(mt0, __shfl_xor_sync(0xffffffffu, mt0, 1));
            mt0 = fmaxf(mt0, __shfl_xor_sync(0xffffffffu, mt0, 2));
            mt1 = fmaxf(mt1, __shfl_xor_sync(0xffffffffu, mt1, 1));
            mt1 = fmaxf(mt1, __shfl_xor_sync(0xffffffffu, mt1, 2));

            const float nm0 = fmaxf(m0, mt0);
            const float nm1 = fmaxf(m1, mt1);
            const float al0 = __expf(m0 - nm0);
            const float al1 = __expf(m1 - nm1);

            float rs0 = 0.f, rs1 = 0.f;
#pragma unroll
            for (int nt = 0; nt < 8; nt++) {
                sA[nt][0] = __expf(sA[nt][0] - nm0);
                sA[nt][1] = __expf(sA[nt][1] - nm0);
                sA[nt][2] = __expf(sA[nt][2] - nm1);
                sA[nt][3] = __expf(sA[nt][3] - nm1);
                rs0 += sA[nt][0] + sA[nt][1];
                rs1 += sA[nt][2] + sA[nt][3];
            }
            rs0 += __shfl_xor_sync(0xffffffffu, rs0, 1);
            rs0 += __shfl_xor_sync(0xffffffffu, rs0, 2);
            rs1 += __shfl_xor_sync(0xffffffffu, rs1, 1);
            rs1 += __shfl_xor_sync(0xffffffffu, rs1, 2);

            l0 = l0 * al0 + rs0;
            l1 = l1 * al1 + rs1;
            m0 = nm0; m1 = nm1;

#pragma unroll
            for (int i = 0; i < 16; i++) {
                o[i][0] *= al0; o[i][1] *= al0;
                o[i][2] *= al1; o[i][3] *= al1;
            }

            unsigned pa_hi[4][4], pa_lo[4][4];
#pragma unroll
            for (int t = 0; t < 4; t++) {
                split2(sA[2 * t][0],     sA[2 * t][1],     pa_hi[t][0], pa_lo[t][0]);
                split2(sA[2 * t][2],     sA[2 * t][3],     pa_hi[t][1], pa_lo[t][1]);
                split2(sA[2 * t + 1][0], sA[2 * t + 1][1], pa_hi[t][2], pa_lo[t][2]);
                split2(sA[2 * t + 1][2], sA[2 * t + 1][3], pa_hi[t][3], pa_lo[t][3]);
            }

#pragma unroll
            for (int t = 0; t < 4; t++) {
#pragma unroll
                for (int np = 0; np < 8; np++) {
                    unsigned vh[4], vl[4];
                    ldsm4t(vh, sVhi + (t * 16 + ldr) * KSTR + np * 16 + ldc);
                    ldsm4t(vl, sVlo + (t * 16 + ldr) * KSTR + np * 16 + ldc);
                    mma_bf16(o[2 * np],     pa_hi[t], vh[0], vh[1]);
                    mma_bf16(o[2 * np],     pa_hi[t], vl[0], vl[1]);
                    mma_bf16(o[2 * np],     pa_lo[t], vh[0], vh[1]);
                    mma_bf16(o[2 * np + 1], pa_hi[t], vh[2], vh[3]);
                    mma_bf16(o[2 * np + 1], pa_hi[t], vl[2], vl[3]);
                    mma_bf16(o[2 * np + 1], pa_lo[t], vh[2], vh[3]);
                }
            }
        }
        __syncthreads();
    }

    // epilogue: normalize + pre-round to tf32 grid (feeds O-GEMM raw-bit MMA)
    const float il0 = 1.f / l0;
    const float il1 = 1.f / l1;
    float* O0 = AO + ((size_t)(b * S_) + qrow0) * QN_ + h * HD_;
    float* O1 = AO + ((size_t)(b * S_) + qrow1) * QN_ + h * HD_;
#pragma unroll
    for (int nt = 0; nt < 16; nt++) {
        *(float2*)(O0 + nt * 8 + 2 * lc) =
            make_float2(round_tf32_f(o[nt][0] * il0), round_tf32_f(o[nt][1] * il0));
        *(float2*)(O1 + nt * 8 + 2 * lc) =
            make_float2(round_tf32_f(o[nt][2] * il1), round_tf32_f(o[nt][3] * il1));
    }
}

// ---------------------------------------------------------------------------
// Launcher
// ---------------------------------------------------------------------------
extern "C" void kernel_launch(void* const* d_in, const int* in_sizes, int n_in,
                              void* d_out, int out_size)
{
    const float* X   = (const float*)d_in[0];
    const int*   pos = (const int*)  d_in[1];
    const float* Wq  = (const float*)d_in[2];
    const float* bq  = (const float*)d_in[3];
    const float* Wk  = (const float*)d_in[4];
    const float* bk  = (const float*)d_in[5];
    const float* Wv  = (const float*)d_in[6];
    const float* bv  = (const float*)d_in[7];
    const float* Wo  = (const float*)d_in[8];
    float* out = (float*)d_out;

    float *Qb, *Kb, *Vb, *AOb, *Xr, *Wqr, *Wkr, *Wvr, *Wor;
    __nv_bfloat16 *Khi, *Klo, *Vhi, *Vlo;
    cudaGetSymbolAddress((void**)&Qb,  g_Q);
    cudaGetSymbolAddress((void**)&Kb,  g_K);
    cudaGetSymbolAddress((void**)&Vb,  g_V);
    cudaGetSymbolAddress((void**)&AOb, g_AO);
    cudaGetSymbolAddress((void**)&Xr,  g_Xr);
    cudaGetSymbolAddress((void**)&Wqr, g_Wq);
    cudaGetSymbolAddress((void**)&Wkr, g_Wk);
    cudaGetSymbolAddress((void**)&Wvr, g_Wv);
    cudaGetSymbolAddress((void**)&Wor, g_Wo);
    cudaGetSymbolAddress((void**)&Khi, g_Khi);
    cudaGetSymbolAddress((void**)&Klo, g_Klo);
    cudaGetSymbolAddress((void**)&Vhi, g_Vhi);
    cudaGetSymbolAddress((void**)&Vlo, g_Vlo);

    cudaFuncSetAttribute(attn_mma, cudaFuncAttributeMaxDynamicSharedMemorySize, ATT_SMEM);

    const int PR_BLOCKS = 1184;
    preround_kernel<<<PR_BLOCKS, 256>>>(X,  Xr,  M_ * H_);
    preround_kernel<<<PR_BLOCKS, 256>>>(Wq, Wqr, H_ * QN_);
    preround_kernel<<<PR_BLOCKS, 256>>>(Wk, Wkr, H_ * KN_);
    preround_kernel<<<PR_BLOCKS, 256>>>(Wv, Wvr, H_ * KN_);
    preround_kernel<<<PR_BLOCKS, 256>>>(Wo, Wor, QN_ * H_);

    gemm_tf32<<<dim3(QN_ / 128, M_ / 128), 256>>>(Xr, Wqr, bq, Qb, M_, QN_, H_);
    gemm_tf32<<<dim3(KN_ / 128, M_ / 128), 256>>>(Xr, Wkr, bk, Kb, M_, KN_, H_);
    gemm_tf32<<<dim3(KN_ / 128, M_ / 128), 256>>>(Xr, Wvr, bv, Vb, M_, KN_, H_);

    // RoPE: Q in-place (pre-scaled), K -> bf16 hi/lo
    rope_kernel<<<dim3(M_, NH_ + NKV_), 128>>>(Qb, Kb, Khi, Klo, pos);
    // V -> bf16 hi/lo
    split_kernel<<<PR_BLOCKS, 256>>>(Vb, Vhi, Vlo, M_ * KN_);

    attn_mma<<<dim3(S_ / ATQ, NH_, B_), AT_THREADS, ATT_SMEM>>>(
        Qb, Khi, Klo, Vhi, Vlo, AOb);

    gemm_tf32<<<dim3(QN_ / 128, M_ / 128), 256>>>(AOb, Wor, nullptr, out, M_, QN_, H_);
}

// round 7
// speedup vs baseline: 1.0382x; 1.0382x over previous
#include <cuda_runtime.h>
#include <cuda_bf16.h>
#include <math.h>
#include <stdint.h>

// Problem constants
#define B_  2
#define S_  2048
#define H_  4096
#define NH_ 32
#define NKV_ 8
#define HD_ 128
#define M_  (B_ * S_)          // 4096 rows
#define QN_ (NH_ * HD_)        // 4096
#define KN_ (NKV_ * HD_)       // 1024
#define QKV_N (QN_ + 2 * KN_)  // 6144

// Scratch (device globals; no allocations allowed)
__device__ float g_Xr[M_ * H_];          // pre-rounded X
__device__ float g_Wqkv[H_ * QKV_N];     // concat pre-rounded [H][6144]
__device__ float g_bqkv[QKV_N];
__device__ float g_QKV[M_ * QKV_N];      // fused projection output
__device__ float g_Wo[QN_ * H_];         // pre-rounded Wo
__device__ float g_AO[M_ * QN_];
__device__ __nv_bfloat16 g_Khi[M_ * KN_], g_Klo[M_ * KN_];
__device__ __nv_bfloat16 g_Vhi[M_ * KN_], g_Vlo[M_ * KN_];

__device__ __forceinline__ float round_tf32_f(float f) {
    unsigned r;
    asm("cvt.rna.tf32.f32 %0, %1;" : "=r"(r) : "f"(f));
    return __uint_as_float(r);
}

__device__ __forceinline__ void split2(float x, float y, unsigned& hi, unsigned& lo)
{
    __nv_bfloat162 h = __floats2bfloat162_rn(x, y);
    float hx = __bfloat162float(h.x), hy = __bfloat162float(h.y);
    __nv_bfloat162 l = __floats2bfloat162_rn(x - hx, y - hy);
    hi = *(unsigned*)&h;
    lo = *(unsigned*)&l;
}

// grid-stride pre-round to tf32 grid
__global__ __launch_bounds__(256)
void preround_kernel(const float* __restrict__ in, float* __restrict__ out, int n)
{
    int i = (blockIdx.x * 256 + threadIdx.x) * 4;
    const int stride = gridDim.x * 1024;
    for (; i < n; i += stride) {
        float4 v = *(const float4*)(in + i);
        v.x = round_tf32_f(v.x);
        v.y = round_tf32_f(v.y);
        v.z = round_tf32_f(v.z);
        v.w = round_tf32_f(v.w);
        *(float4*)(out + i) = v;
    }
}

// pre-round + scatter into the concatenated [H][6144] weight buffer
__global__ __launch_bounds__(256)
void concat_preround(const float* __restrict__ src, float* __restrict__ dst,
                     int N_src, int col0, int n)
{
    int i = (blockIdx.x * 256 + threadIdx.x) * 4;
    const int stride = gridDim.x * 1024;
    for (; i < n; i += stride) {
        float4 v = *(const float4*)(src + i);
        v.x = round_tf32_f(v.x);
        v.y = round_tf32_f(v.y);
        v.z = round_tf32_f(v.z);
        v.w = round_tf32_f(v.w);
        const int row = i / N_src, c = i - row * N_src;
        *(float4*)(dst + (size_t)row * QKV_N + col0 + c) = v;
    }
}

__global__ __launch_bounds__(256)
void bias_concat(const float* __restrict__ bq, const float* __restrict__ bk,
                 const float* __restrict__ bv, float* __restrict__ dst)
{
    const int j = blockIdx.x * 256 + threadIdx.x;
    if (j < QN_)              dst[j] = bq[j];
    else if (j < QN_ + KN_)   dst[j] = bk[j - QN_];
    else if (j < QKV_N)       dst[j] = bv[j - QN_ - KN_];
}

// ---------------------------------------------------------------------------
// TF32 tensor-core GEMM (R4, unchanged): inputs pre-rounded -> raw-bit MMA.
// ---------------------------------------------------------------------------
#define AS_STRIDE 20
#define BS_STRIDE 136
#define STAGE_FLOATS (128 * AS_STRIDE + 16 * BS_STRIDE)

__device__ __forceinline__ void mma_tf32(float& d0, float& d1, float& d2, float& d3,
                                         unsigned a0, unsigned a1, unsigned a2, unsigned a3,
                                         unsigned b0, unsigned b1)
{
    asm volatile(
        "mma.sync.aligned.m16n8k8.row.col.f32.tf32.tf32.f32 "
        "{%0,%1,%2,%3}, {%4,%5,%6,%7}, {%8,%9}, {%0,%1,%2,%3};"
        : "+f"(d0), "+f"(d1), "+f"(d2), "+f"(d3)
        : "r"(a0), "r"(a1), "r"(a2), "r"(a3), "r"(b0), "r"(b1));
}

__device__ __forceinline__ void cp_async16(void* smem_dst, const void* gsrc) {
    unsigned dst = (unsigned)__cvta_generic_to_shared(smem_dst);
    asm volatile("cp.async.cg.shared.global [%0], [%1], 16;" :: "r"(dst), "l"(gsrc));
}

__global__ __launch_bounds__(256)
void gemm_tf32(const float* __restrict__ A, const float* __restrict__ B,
               const float* __restrict__ bias, float* __restrict__ C,
               int M, int N, int K)
{
    __shared__ float smem[2 * STAGE_FLOATS];

    const int tid  = threadIdx.x;
    const int wid  = tid >> 5;
    const int lane = tid & 31;
    const int warp_m = (wid & 1) * 64;
    const int warp_n = (wid >> 1) * 32;
    const int brow = blockIdx.y * 128;
    const int bcol = blockIdx.x * 128;
    const int lr = lane >> 2;
    const int lc = lane & 3;

    float acc[4][4][4];
#pragma unroll
    for (int mt = 0; mt < 4; mt++)
#pragma unroll
        for (int nt = 0; nt < 4; nt++)
#pragma unroll
            for (int i = 0; i < 4; i++) acc[mt][nt][i] = 0.f;

    const int a_row0 = tid >> 2;
    const int a_col  = (tid & 3) * 4;
    const int b_row0 = tid >> 5;
    const int b_col  = (tid & 31) * 4;

    auto load_stage = [&](int s, int k0) {
        float* Asm = smem + s * STAGE_FLOATS;
        float* Bsm = Asm + 128 * AS_STRIDE;
#pragma unroll
        for (int it = 0; it < 2; it++) {
            int r = a_row0 + it * 64;
            cp_async16(&Asm[r * AS_STRIDE + a_col],
                       &A[(size_t)(brow + r) * K + k0 + a_col]);
        }
#pragma unroll
        for (int it = 0; it < 2; it++) {
            int r = b_row0 + it * 8;
            cp_async16(&Bsm[r * BS_STRIDE + b_col],
                       &B[(size_t)(k0 + r) * N + bcol + b_col]);
        }
        asm volatile("cp.async.commit_group;");
    };

    const int KT = K / 16;
    load_stage(0, 0);

    for (int kt = 0; kt < KT; kt++) {
        const int s = kt & 1;
        if (kt + 1 < KT) {
            load_stage(s ^ 1, (kt + 1) * 16);
            asm volatile("cp.async.wait_group 1;");
        } else {
            asm volatile("cp.async.wait_group 0;");
        }
        __syncthreads();

        const float* Asm = smem + s * STAGE_FLOATS;
        const float* Bsm = Asm + 128 * AS_STRIDE;

#pragma unroll
        for (int ks = 0; ks < 2; ks++) {
            const int k0 = ks * 8;
            unsigned af[4][4], bf[4][2];
#pragma unroll
            for (int mt = 0; mt < 4; mt++) {
                const float* ap = Asm + (warp_m + mt * 16 + lr) * AS_STRIDE + k0 + lc;
                af[mt][0] = __float_as_uint(ap[0]);
                af[mt][1] = __float_as_uint(ap[8 * AS_STRIDE]);
                af[mt][2] = __float_as_uint(ap[4]);
                af[mt][3] = __float_as_uint(ap[8 * AS_STRIDE + 4]);
            }
#pragma unroll
            for (int nt = 0; nt < 4; nt++) {
                const float* bp = Bsm + (k0 + lc) * BS_STRIDE + warp_n + nt * 8 + lr;
                bf[nt][0] = __float_as_uint(bp[0]);
                bf[nt][1] = __float_as_uint(bp[4 * BS_STRIDE]);
            }
#pragma unroll
            for (int mt = 0; mt < 4; mt++)
#pragma unroll
                for (int nt = 0; nt < 4; nt++)
                    mma_tf32(acc[mt][nt][0], acc[mt][nt][1], acc[mt][nt][2], acc[mt][nt][3],
                             af[mt][0], af[mt][1], af[mt][2], af[mt][3],
                             bf[nt][0], bf[nt][1]);
        }
        __syncthreads();
    }

#pragma unroll
    for (int mt = 0; mt < 4; mt++) {
#pragma unroll
        for (int nt = 0; nt < 4; nt++) {
            const int row0 = brow + warp_m + mt * 16 + lr;
            const int col  = bcol + warp_n + nt * 8 + lc * 2;
            const float b0 = bias ? bias[col]     : 0.f;
            const float b1 = bias ? bias[col + 1] : 0.f;
            float2 v0 = make_float2(acc[mt][nt][0] + b0, acc[mt][nt][1] + b1);
            float2 v1 = make_float2(acc[mt][nt][2] + b0, acc[mt][nt][3] + b1);
            *(float2*)&C[(size_t)row0 * N + col]       = v0;
            *(float2*)&C[(size_t)(row0 + 8) * N + col] = v1;
        }
    }
}

// ---------------------------------------------------------------------------
// RoPE over fused QKV: Q in-place (pre-scaled); K rotated -> bf16 hi/lo;
// V -> bf16 hi/lo. grid = (M_, 48), 128 threads.
// ---------------------------------------------------------------------------
__global__ __launch_bounds__(128)
void rope48_kernel(float* __restrict__ QKV,
                   __nv_bfloat16* __restrict__ Khi, __nv_bfloat16* __restrict__ Klo,
                   __nv_bfloat16* __restrict__ Vhi, __nv_bfloat16* __restrict__ Vlo,
                   const int* __restrict__ pos_ids)
{
    const int row  = blockIdx.x;
    const int head = blockIdx.y;
    const int d    = threadIdx.x;

    if (head >= NH_ + NKV_) {
        // V: split only
        const int kvh = head - NH_ - NKV_;
        const float v = QKV[(size_t)row * QKV_N + QN_ + KN_ + kvh * HD_ + d];
        const __nv_bfloat16 h = __float2bfloat16(v);
        const size_t off = (size_t)row * KN_ + kvh * HD_;
        Vhi[off + d] = h;
        Vlo[off + d] = __float2bfloat16(v - __bfloat162float(h));
        return;
    }

    const int pos = pos_ids[row];
    const int i = d & 63;
    const float inv_freq = exp2f(-(float)(2 * i) * (1.0f / 128.0f) * 13.28771238f);
    const float ang = (float)pos * inv_freq;
    float c, s;
    sincosf(ang, &s, &c);

    if (head < NH_) {
        float* base = QKV + (size_t)row * QKV_N + head * HD_;
        const float x = base[d];
        const float other = (d < 64) ? -base[d + 64] : base[d - 64];
        const float v = (x * c + other * s) * 0.08838834764831845f;
        __syncthreads();
        base[d] = v;
    } else {
        const int kvh = head - NH_;
        const float* base = QKV + (size_t)row * QKV_N + QN_ + kvh * HD_;
        const float x = base[d];
        const float other = (d < 64) ? -base[d + 64] : base[d - 64];
        const float v = x * c + other * s;
        const __nv_bfloat16 h = __float2bfloat16(v);
        const size_t off = (size_t)row * KN_ + kvh * HD_;
        Khi[off + d] = h;
        Klo[off + d] = __float2bfloat16(v - __bfloat162float(h));
    }
}

// ---------------------------------------------------------------------------
// Tensor-core flash attention, bf16x3. 64 queries/block, 4 warps, 64-key
// tiles. K/V pre-split bf16 in global; cp.async overlap: V-load || QK,
// K(next)-load || PV. ldmatrix.x4 for both K and V fragments.
// ---------------------------------------------------------------------------
#define BQ 64
#define BK 64
#define KSTR 136                       // bf16 elements per row (128 + 8 pad)
#define ABUF (BK * KSTR * 2)           // 17408 B per buffer
#define ATT_SMEM (4 * ABUF)            // Khi, Klo, Vhi, Vlo = 69632 B

__device__ __forceinline__ void mma_bf16(float c[4], const unsigned a[4],
                                         unsigned b0, unsigned b1)
{
    asm volatile(
        "mma.sync.aligned.m16n8k16.row.col.f32.bf16.bf16.f32 "
        "{%0,%1,%2,%3}, {%4,%5,%6,%7}, {%8,%9}, {%0,%1,%2,%3};"
        : "+f"(c[0]), "+f"(c[1]), "+f"(c[2]), "+f"(c[3])
        : "r"(a[0]), "r"(a[1]), "r"(a[2]), "r"(a[3]), "r"(b0), "r"(b1));
}

__device__ __forceinline__ void ldsm4(unsigned r[4], const void* p)
{
    unsigned a = (unsigned)__cvta_generic_to_shared(p);
    asm volatile(
        "ldmatrix.sync.aligned.m8n8.x4.shared.b16 {%0,%1,%2,%3}, [%4];"
        : "=r"(r[0]), "=r"(r[1]), "=r"(r[2]), "=r"(r[3]) : "r"(a));
}

__device__ __forceinline__ void ldsm4t(unsigned r[4], const void* p)
{
    unsigned a = (unsigned)__cvta_generic_to_shared(p);
    asm volatile(
        "ldmatrix.sync.aligned.m8n8.x4.trans.shared.b16 {%0,%1,%2,%3}, [%4];"
        : "=r"(r[0]), "=r"(r[1]), "=r"(r[2]), "=r"(r[3]) : "r"(a));
}

__global__ __launch_bounds__(128)
void attn_mma(const float* __restrict__ QKV,
              const __nv_bfloat16* __restrict__ Khi, const __nv_bfloat16* __restrict__ Klo,
              const __nv_bfloat16* __restrict__ Vhi, const __nv_bfloat16* __restrict__ Vlo,
              float* __restrict__ AO)
{
    extern __shared__ char smraw[];
    __nv_bfloat16* sKhi = (__nv_bfloat16*)(smraw);
    __nv_bfloat16* sKlo = (__nv_bfloat16*)(smraw + ABUF);
    __nv_bfloat16* sVhi = (__nv_bfloat16*)(smraw + 2 * ABUF);
    __nv_bfloat16* sVlo = (__nv_bfloat16*)(smraw + 3 * ABUF);

    const int qt = blockIdx.x, h = blockIdx.y, b = blockIdx.z;
    const int q0 = qt * BQ;
    const int kvh = h >> 2;
    const int tid = threadIdx.x;
    const int w = tid >> 5, lane = tid & 31;
    const int lr = lane >> 2, lc = lane & 3;

    const int qrow0 = q0 + w * 16 + lr;
    const int qrow1 = qrow0 + 8;

    // Q fragments (pre-scaled by rope), hi/lo split, in registers
    unsigned qa_hi[8][4], qa_lo[8][4];
    {
        const float* Q0 = QKV + ((size_t)(b * S_) + qrow0) * QKV_N + h * HD_;
        const float* Q1 = QKV + ((size_t)(b * S_) + qrow1) * QKV_N + h * HD_;
#pragma unroll
        for (int kt = 0; kt < 8; kt++) {
            float2 v;
            v = *(const float2*)(Q0 + kt * 16 + 2 * lc);
            split2(v.x, v.y, qa_hi[kt][0], qa_lo[kt][0]);
            v = *(const float2*)(Q1 + kt * 16 + 2 * lc);
            split2(v.x, v.y, qa_hi[kt][1], qa_lo[kt][1]);
            v = *(const float2*)(Q0 + kt * 16 + 2 * lc + 8);
            split2(v.x, v.y, qa_hi[kt][2], qa_lo[kt][2]);
            v = *(const float2*)(Q1 + kt * 16 + 2 * lc + 8);
            split2(v.x, v.y, qa_hi[kt][3], qa_lo[kt][3]);
        }
    }

    float m0 = -1e30f, m1 = -1e30f, l0 = 0.f, l1 = 0.f;
    float o[16][4];
#pragma unroll
    for (int i = 0; i < 16; i++)
#pragma unroll
        for (int j = 0; j < 4; j++) o[i][j] = 0.f;

    const int nTiles = qt + 1;
    const int wEnd = q0 + w * 16 + 16;
    const int ldr = (lane & 7) + ((lane >> 3) & 1) * 8;  // ldmatrix.trans row
    const int ldc = ((lane >> 4) & 1) * 8;               // ldmatrix.trans col off
    const int klr = lane & 7;                            // ldmatrix row
    const int kmg = lane >> 3;                           // ldmatrix matrix group

    const size_t kv_base = (size_t)(b * S_) * KN_ + kvh * HD_;

    // per-thread load decomposition: 8 x 16B chunks per buffer
    auto load_pair = [&](__nv_bfloat16* dhi, __nv_bfloat16* dlo,
                         const __nv_bfloat16* ghi, const __nv_bfloat16* glo, int kbase) {
        const size_t off = kv_base + (size_t)kbase * KN_;
#pragma unroll
        for (int j = 0; j < 8; j++) {
            const int idx = tid + 128 * j;      // 0..1023
            const int row = idx >> 4, c16 = idx & 15;
            const size_t g = off + (size_t)row * KN_ + c16 * 8;
            cp_async16(dhi + row * KSTR + c16 * 8, ghi + g);
            cp_async16(dlo + row * KSTR + c16 * 8, glo + g);
        }
        asm volatile("cp.async.commit_group;");
    };

    load_pair(sKhi, sKlo, Khi, Klo, 0);
    asm volatile("cp.async.wait_group 0;");
    __syncthreads();

    for (int kt = 0; kt < nTiles; kt++) {
        const int kbase = kt * BK;
        const bool active = kbase < wEnd;

        // V load overlaps QK compute
        load_pair(sVhi, sVlo, Vhi, Vlo, kbase);

        float sA[8][4];
        unsigned pa_hi[4][4], pa_lo[4][4];

        if (active) {
#pragma unroll
            for (int nt = 0; nt < 8; nt++)
#pragma unroll
                for (int j = 0; j < 4; j++) sA[nt][j] = 0.f;

#pragma unroll
            for (int dkt2 = 0; dkt2 < 4; dkt2++) {
                const int col = dkt2 * 32 + kmg * 8;
#pragma unroll
                for (int nt = 0; nt < 8; nt++) {
                    unsigned bh[4], bl[4];
                    ldsm4(bh, sKhi + (nt * 8 + klr) * KSTR + col);
                    ldsm4(bl, sKlo + (nt * 8 + klr) * KSTR + col);
                    mma_bf16(sA[nt], qa_hi[2 * dkt2],     bh[0], bh[1]);
                    mma_bf16(sA[nt], qa_hi[2 * dkt2],     bl[0], bl[1]);
                    mma_bf16(sA[nt], qa_lo[2 * dkt2],     bh[0], bh[1]);
                    mma_bf16(sA[nt], qa_hi[2 * dkt2 + 1], bh[2], bh[3]);
                    mma_bf16(sA[nt], qa_hi[2 * dkt2 + 1], bl[2], bl[3]);
                    mma_bf16(sA[nt], qa_lo[2 * dkt2 + 1], bh[2], bh[3]);
                }
            }

            if (kbase + BK > qrow0) {
#pragma unroll
                for (int nt = 0; nt < 8; nt++) {
                    const int j0 = kbase + nt * 8 + 2 * lc;
                    if (j0 > qrow0)     sA[nt][0] = -1e30f;
                    if (j0 + 1 > qrow0) sA[nt][1] = -1e30f;
                    if (j0 > qrow1)     sA[nt][2] = -1e30f;
                    if (j0 + 1 > qrow1) sA[nt][3] = -1e30f;
                }
            }

            float mt0 = -1e30f, mt1 = -1e30f;
#pragma unroll
            for (int nt = 0; nt < 8; nt++) {
                mt0 = fmaxf(mt0, fmaxf(sA[nt][0], sA[nt][1]));
                mt1 = fmaxf(mt1, fmaxf(sA[nt][2], sA[nt][3]));
            }
            mt0 = fmaxf(mt0, __shfl_xor_sync(0xffffffffu, mt0, 1));
            mt0 = fmaxf(mt0, __shfl_xor_sync(0xffffffffu, mt0, 2));
            mt1 = fmaxf(mt1, __shfl_xor_sync(0xffffffffu, mt1, 1));
            mt1 = fmaxf(mt1, __shfl_xor_sync(0xffffffffu, mt1, 2));

            const float nm0 = fmaxf(m0, mt0);
            const float nm1 = fmaxf(m1, mt1);
            const float al0 = __expf(m0 - nm0);
            const float al1 = __expf(m1 - nm1);

            float rs0 = 0.f, rs1 = 0.f;
#pragma unroll
            for (int nt = 0; nt < 8; nt++) {
                sA[nt][0] = __expf(sA[nt][0] - nm0);
                sA[nt][1] = __expf(sA[nt][1] - nm0);
                sA[nt][2] = __expf(sA[nt][2] - nm1);
                sA[nt][3] = __expf(sA[nt][3] - nm1);
                rs0 += sA[nt][0] + sA[nt][1];
                rs1 += sA[nt][2] + sA[nt][3];
            }
            rs0 += __shfl_xor_sync(0xffffffffu, rs0, 1);
            rs0 += __shfl_xor_sync(0xffffffffu, rs0, 2);
            rs1 += __shfl_xor_sync(0xffffffffu, rs1, 1);
            rs1 += __shfl_xor_sync(0xffffffffu, rs1, 2);

            l0 = l0 * al0 + rs0;
            l1 = l1 * al1 + rs1;
            m0 = nm0; m1 = nm1;

#pragma unroll
            for (int i = 0; i < 16; i++) {
                o[i][0] *= al0; o[i][1] *= al0;
                o[i][2] *= al1; o[i][3] *= al1;
            }

#pragma unroll
            for (int t = 0; t < 4; t++) {
                split2(sA[2 * t][0],     sA[2 * t][1],     pa_hi[t][0], pa_lo[t][0]);
                split2(sA[2 * t][2],     sA[2 * t][3],     pa_hi[t][1], pa_lo[t][1]);
                split2(sA[2 * t + 1][0], sA[2 * t + 1][1], pa_hi[t][2], pa_lo[t][2]);
                split2(sA[2 * t + 1][2], sA[2 * t + 1][3], pa_hi[t][3], pa_lo[t][3]);
            }
        }

        // V must be resident; all warps done reading K
        asm volatile("cp.async.wait_group 0;");
        __syncthreads();

        // K(next) load overlaps PV compute
        if (kt + 1 < nTiles) load_pair(sKhi, sKlo, Khi, Klo, kbase + BK);

        if (active) {
#pragma unroll
            for (int t = 0; t < 4; t++) {
#pragma unroll
                for (int np = 0; np < 8; np++) {
                    unsigned vh[4], vl[4];
                    ldsm4t(vh, sVhi + (t * 16 + ldr) * KSTR + np * 16 + ldc);
                    ldsm4t(vl, sVlo + (t * 16 + ldr) * KSTR + np * 16 + ldc);
                    mma_bf16(o[2 * np],     pa_hi[t], vh[0], vh[1]);
                    mma_bf16(o[2 * np],     pa_hi[t], vl[0], vl[1]);
                    mma_bf16(o[2 * np],     pa_lo[t], vh[0], vh[1]);
                    mma_bf16(o[2 * np + 1], pa_hi[t], vh[2], vh[3]);
                    mma_bf16(o[2 * np + 1], pa_hi[t], vl[2], vl[3]);
                    mma_bf16(o[2 * np + 1], pa_lo[t], vh[2], vh[3]);
                }
            }
        }

        // K(next) resident; all warps done reading V
        asm volatile("cp.async.wait_group 0;");
        __syncthreads();
    }

    // epilogue: normalize + pre-round to tf32 grid (feeds O-GEMM)
    const float il0 = 1.f / l0;
    const float il1 = 1.f / l1;
    float* O0 = AO + ((size_t)(b * S_) + qrow0) * QN_ + h * HD_;
    float* O1 = AO + ((size_t)(b * S_) + qrow1) * QN_ + h * HD_;
#pragma unroll
    for (int nt = 0; nt < 16; nt++) {
        *(float2*)(O0 + nt * 8 + 2 * lc) =
            make_float2(round_tf32_f(o[nt][0] * il0), round_tf32_f(o[nt][1] * il0));
        *(float2*)(O1 + nt * 8 + 2 * lc) =
            make_float2(round_tf32_f(o[nt][2] * il1), round_tf32_f(o[nt][3] * il1));
    }
}

// ---------------------------------------------------------------------------
// Launcher
// ---------------------------------------------------------------------------
extern "C" void kernel_launch(void* const* d_in, const int* in_sizes, int n_in,
                              void* d_out, int out_size)
{
    const float* X   = (const float*)d_in[0];
    const int*   pos = (const int*)  d_in[1];
    const float* Wq  = (const float*)d_in[2];
    const float* bq  = (const float*)d_in[3];
    const float* Wk  = (const float*)d_in[4];
    const float* bk  = (const float*)d_in[5];
    const float* Wv  = (const float*)d_in[6];
    const float* bv  = (const float*)d_in[7];
    const float* Wo  = (const float*)d_in[8];
    float* out = (float*)d_out;

    float *Xr, *Wqkv, *bqkv, *QKV, *Wor, *AOb;
    __nv_bfloat16 *Khi, *Klo, *Vhi, *Vlo;
    cudaGetSymbolAddress((void**)&Xr,   g_Xr);
    cudaGetSymbolAddress((void**)&Wqkv, g_Wqkv);
    cudaGetSymbolAddress((void**)&bqkv, g_bqkv);
    cudaGetSymbolAddress((void**)&QKV,  g_QKV);
    cudaGetSymbolAddress((void**)&Wor,  g_Wo);
    cudaGetSymbolAddress((void**)&AOb,  g_AO);
    cudaGetSymbolAddress((void**)&Khi,  g_Khi);
    cudaGetSymbolAddress((void**)&Klo,  g_Klo);
    cudaGetSymbolAddress((void**)&Vhi,  g_Vhi);
    cudaGetSymbolAddress((void**)&Vlo,  g_Vlo);

    cudaFuncSetAttribute(attn_mma, cudaFuncAttributeMaxDynamicSharedMemorySize, ATT_SMEM);

    const int PR_BLOCKS = 1184;
    preround_kernel<<<PR_BLOCKS, 256>>>(X,  Xr,  M_ * H_);
    concat_preround<<<PR_BLOCKS, 256>>>(Wq, Wqkv, QN_, 0,         H_ * QN_);
    concat_preround<<<PR_BLOCKS, 256>>>(Wk, Wqkv, KN_, QN_,       H_ * KN_);
    concat_preround<<<PR_BLOCKS, 256>>>(Wv, Wqkv, KN_, QN_ + KN_, H_ * KN_);
    bias_concat<<<QKV_N / 256, 256>>>(bq, bk, bv, bqkv);
    preround_kernel<<<PR_BLOCKS, 256>>>(Wo, Wor, QN_ * H_);

    // Fused QKV projection
    gemm_tf32<<<dim3(QKV_N / 128, M_ / 128), 256>>>(Xr, Wqkv, bqkv, QKV, M_, QKV_N, H_);

    // RoPE + K/V split
    rope48_kernel<<<dim3(M_, NH_ + 2 * NKV_), 128>>>(QKV, Khi, Klo, Vhi, Vlo, pos);

    // Attention
    attn_mma<<<dim3(S_ / BQ, NH_, B_), 128, ATT_SMEM>>>(QKV, Khi, Klo, Vhi, Vlo, AOb);

    // Output projection
    gemm_tf32<<<dim3(QN_ / 128, M_ / 128), 256>>>(AOb, Wor, nullptr, out, M_, QN_, H_);
}